// round 8
// baseline (speedup 1.0000x reference)
#include <cuda_runtime.h>

// RoiPoolingConv: ROI-Align bilinear pooling, POOL=7
// img:  (8, 64, 64, 1024) float32, NHWC (channels contiguous)
// rois: (32, 4) int32  [x, y, w, h]
// out:  flat index ((r*8 + b)*7 + py)*7 + px, 1024 channels contiguous
//
// R8: occupancy-first. Cross-round data shows achieved HBM BW tracks
// warps_active (R1 occ 79.5% -> 5471 GB/s was the best mover). So: the R1
// shape (1 tile per 256-thread CTA, 4 LDG.128/thread), minimum registers
// (32-bit offset math, forced 8 CTAs/SM via launch bounds), plus the __stcs
// store win from R4.

#define N_ROIS 32
#define N_BATCH 8
#define POOLP 7
#define CH 1024
#define IMG_W 64
#define IMG_H 64
#define N_TILES (N_ROIS * N_BATCH * POOLP * POOLP)   // 12544

__global__ void __launch_bounds__(256, 8) roi_align_kernel_v8(
    const float* __restrict__ img,
    const int*   __restrict__ rois,
    float*       __restrict__ out)
{
    const int flat = blockIdx.x;            // 0 .. 12543
    const int px = flat % POOLP;
    const int py = (flat / POOLP) % POOLP;
    const int b  = (flat / (POOLP * POOLP)) % N_BATCH;
    const int r  = flat / (POOLP * POOLP * N_BATCH);

    const int rx = __ldg(&rois[r * 4 + 0]);
    const int ry = __ldg(&rois[r * 4 + 1]);
    const int rw = __ldg(&rois[r * 4 + 2]);
    const int rh = __ldg(&rois[r * 4 + 3]);

    // coord = (p+0.5)*(size/POOL) - 0.5 (matches reference _edge)
    const float cx = ((float)px + 0.5f) * ((float)rw * (1.0f / POOLP)) - 0.5f;
    const float fx = floorf(cx);
    const int lox = max((int)fx, 0);
    const int hix = min(max((int)ceilf(cx), 0), rw - 1);
    const float wx = cx - fx;
    const int x0 = rx + lox;
    const int x1 = rx + hix;

    const float cy = ((float)py + 0.5f) * ((float)rh * (1.0f / POOLP)) - 0.5f;
    const float fy = floorf(cy);
    const int loy = max((int)fy, 0);
    const int hiy = min(max((int)ceilf(cy), 0), rh - 1);
    const float wy = cy - fy;
    const int y0 = ry + loy;
    const int y1 = ry + hiy;

    // All offsets fit in 32 bits (image = 33.5M floats, out = 12.8M floats):
    // keep index math in uint32, single wide add at the dereference.
    const unsigned t = threadIdx.x;         // 256 threads * float4 = 1024 ch
    const unsigned base_b = (unsigned)b * (IMG_H * IMG_W * (CH / 4));  // float4 units
    const unsigned row0 = base_b + ((unsigned)y0 * IMG_W) * (CH / 4) + t;
    const unsigned row1 = base_b + ((unsigned)y1 * IMG_W) * (CH / 4) + t;

    const float4* __restrict__ img4 = (const float4*)img;

    const float4 a = __ldg(img4 + row0 + (unsigned)x0 * (CH / 4));
    const float4 bq = __ldg(img4 + row0 + (unsigned)x1 * (CH / 4));
    const float4 c = __ldg(img4 + row1 + (unsigned)x0 * (CH / 4));
    const float4 d = __ldg(img4 + row1 + (unsigned)x1 * (CH / 4));

    float4 res;
    {
        float top, bot;
        top = a.x + (bq.x - a.x) * wx;
        bot = c.x + (d.x - c.x) * wx;
        res.x = top + (bot - top) * wy;
        top = a.y + (bq.y - a.y) * wx;
        bot = c.y + (d.y - c.y) * wx;
        res.y = top + (bot - top) * wy;
        top = a.z + (bq.z - a.z) * wx;
        bot = c.z + (d.z - c.z) * wx;
        res.z = top + (bot - top) * wy;
        top = a.w + (bq.w - a.w) * wx;
        bot = c.w + (d.w - c.w) * wx;
        res.w = top + (bot - top) * wy;
    }

    __stcs((float4*)out + (unsigned)flat * (CH / 4) + t, res);
}

extern "C" void kernel_launch(void* const* d_in, const int* in_sizes, int n_in,
                              void* d_out, int out_size)
{
    const float* img  = (const float*)d_in[0];
    const int*   rois = (const int*)d_in[1];
    float*       out  = (float*)d_out;

    roi_align_kernel_v8<<<N_TILES, 256>>>(img, rois, out);
}

// round 9
// speedup vs baseline: 1.0580x; 1.0580x over previous
#include <cuda_runtime.h>

// RoiPoolingConv: ROI-Align bilinear pooling, POOL=7
// img:  (8, 64, 64, 1024) float32, NHWC (channels contiguous)
// rois: (32, 4) int32  [x, y, w, h]
// out:  flat index ((r*8 + b)*7 + py)*7 + px, 1024 channels contiguous
//
// R9: R8's occupancy-optimal body (regs~30, 8 CTAs/SM, uint32 addressing,
// __stcs) + a blockIdx->tile interleave that co-schedules ROI r with ROI
// r+16. Cross-round data showed DRAM traffic is scheduling-dependent:
// R4's (flat, flat+6272) pairing co-resided spatially-overlapping ROIs in
// L2 (reads 96MB) while flat order refetches (reads 140MB). This remap
// recreates that L2-friendly order at full occupancy.

#define N_ROIS 32
#define N_BATCH 8
#define POOLP 7
#define CH 1024
#define IMG_W 64
#define IMG_H 64
#define N_TILES (N_ROIS * N_BATCH * POOLP * POOLP)   // 12544
#define HALF_TILES (N_TILES / 2)                     // 6272

__global__ void __launch_bounds__(256, 8) roi_align_kernel_v9(
    const float* __restrict__ img,
    const int*   __restrict__ rois,
    float*       __restrict__ out)
{
    // Interleave lower/upper halves: consecutive CTAs alternate ROI r and
    // ROI r+16 (spatially overlapping pairs -> co-resident in L2).
    const int blk  = blockIdx.x;
    const int flat = (blk >> 1) + ((blk & 1) ? HALF_TILES : 0);

    const int px = flat % POOLP;
    const int py = (flat / POOLP) % POOLP;
    const int b  = (flat / (POOLP * POOLP)) % N_BATCH;
    const int r  = flat / (POOLP * POOLP * N_BATCH);

    const int rx = __ldg(&rois[r * 4 + 0]);
    const int ry = __ldg(&rois[r * 4 + 1]);
    const int rw = __ldg(&rois[r * 4 + 2]);
    const int rh = __ldg(&rois[r * 4 + 3]);

    // coord = (p+0.5)*(size/POOL) - 0.5 (matches reference _edge)
    const float cx = ((float)px + 0.5f) * ((float)rw * (1.0f / POOLP)) - 0.5f;
    const float fx = floorf(cx);
    const int lox = max((int)fx, 0);
    const int hix = min(max((int)ceilf(cx), 0), rw - 1);
    const float wx = cx - fx;
    const int x0 = rx + lox;
    const int x1 = rx + hix;

    const float cy = ((float)py + 0.5f) * ((float)rh * (1.0f / POOLP)) - 0.5f;
    const float fy = floorf(cy);
    const int loy = max((int)fy, 0);
    const int hiy = min(max((int)ceilf(cy), 0), rh - 1);
    const float wy = cy - fy;
    const int y0 = ry + loy;
    const int y1 = ry + hiy;

    // All offsets fit in uint32 (image = 33.5M floats, out = 12.8M floats).
    const unsigned t = threadIdx.x;         // 256 threads * float4 = 1024 ch
    const unsigned base_b = (unsigned)b * (IMG_H * IMG_W * (CH / 4));  // float4 units
    const unsigned row0 = base_b + ((unsigned)y0 * IMG_W) * (CH / 4) + t;
    const unsigned row1 = base_b + ((unsigned)y1 * IMG_W) * (CH / 4) + t;

    const float4* __restrict__ img4 = (const float4*)img;

    const float4 a = __ldg(img4 + row0 + (unsigned)x0 * (CH / 4));
    const float4 bq = __ldg(img4 + row0 + (unsigned)x1 * (CH / 4));
    const float4 c = __ldg(img4 + row1 + (unsigned)x0 * (CH / 4));
    const float4 d = __ldg(img4 + row1 + (unsigned)x1 * (CH / 4));

    float4 res;
    {
        float top, bot;
        top = a.x + (bq.x - a.x) * wx;
        bot = c.x + (d.x - c.x) * wx;
        res.x = top + (bot - top) * wy;
        top = a.y + (bq.y - a.y) * wx;
        bot = c.y + (d.y - c.y) * wx;
        res.y = top + (bot - top) * wy;
        top = a.z + (bq.z - a.z) * wx;
        bot = c.z + (d.z - c.z) * wx;
        res.z = top + (bot - top) * wy;
        top = a.w + (bq.w - a.w) * wx;
        bot = c.w + (d.w - c.w) * wx;
        res.w = top + (bot - top) * wy;
    }

    __stcs((float4*)out + (unsigned)flat * (CH / 4) + t, res);
}

extern "C" void kernel_launch(void* const* d_in, const int* in_sizes, int n_in,
                              void* d_out, int out_size)
{
    const float* img  = (const float*)d_in[0];
    const int*   rois = (const int*)d_in[1];
    float*       out  = (float*)d_out;

    roi_align_kernel_v9<<<N_TILES, 256>>>(img, rois, out);
}

// round 10
// speedup vs baseline: 1.0645x; 1.0061x over previous
#include <cuda_runtime.h>

// RoiPoolingConv: ROI-Align bilinear pooling, POOL=7
// img:  (8, 64, 64, 1024) float32, NHWC (channels contiguous)
// rois: (32, 4) int32  [x, y, w, h]
// out:  flat index ((r*8 + b)*7 + py)*7 + px, 1024 channels contiguous
//
// R10: batch-OUTERMOST scheduling. The output layout makes batch an inner
// dim (flat = (r*8+b)*49 + ...), so flat-order CTAs interleave all 8 batch
// images (134MB live > 126MB L2) and cross-ROI reuse misses (~37MB/replay
// intra-replay refetch measured in R8). Remapping blk = b*1568 + r*49 + pypx
// keeps only ~1-2 batch images (17-34MB) in flux at a time: all ROI-overlap
// reuse becomes L2 hits, and idle L2 capacity retains other batches across
// graph replays. Body identical to R9 (regs~30, 8 CTAs/SM, __stcs).

#define N_ROIS 32
#define N_BATCH 8
#define POOLP 7
#define CH 1024
#define IMG_W 64
#define IMG_H 64
#define N_TILES (N_ROIS * N_BATCH * POOLP * POOLP)   // 12544
#define TILES_PER_BATCH (N_ROIS * POOLP * POOLP)     // 1568

__global__ void __launch_bounds__(256, 8) roi_align_kernel_v10(
    const float* __restrict__ img,
    const int*   __restrict__ rois,
    float*       __restrict__ out)
{
    // blk -> (batch-outermost) tile
    const int blk  = blockIdx.x;
    const int b    = blk / TILES_PER_BATCH;
    const int rest = blk - b * TILES_PER_BATCH;      // r*49 + py*7 + px
    const int r    = rest / (POOLP * POOLP);
    const int pypx = rest - r * (POOLP * POOLP);
    const int py   = pypx / POOLP;
    const int px   = pypx - py * POOLP;
    const int flat = (r * N_BATCH + b) * (POOLP * POOLP) + pypx;  // output tile

    const int rx = __ldg(&rois[r * 4 + 0]);
    const int ry = __ldg(&rois[r * 4 + 1]);
    const int rw = __ldg(&rois[r * 4 + 2]);
    const int rh = __ldg(&rois[r * 4 + 3]);

    // coord = (p+0.5)*(size/POOL) - 0.5 (matches reference _edge)
    const float cx = ((float)px + 0.5f) * ((float)rw * (1.0f / POOLP)) - 0.5f;
    const float fx = floorf(cx);
    const int lox = max((int)fx, 0);
    const int hix = min(max((int)ceilf(cx), 0), rw - 1);
    const float wx = cx - fx;
    const int x0 = rx + lox;
    const int x1 = rx + hix;

    const float cy = ((float)py + 0.5f) * ((float)rh * (1.0f / POOLP)) - 0.5f;
    const float fy = floorf(cy);
    const int loy = max((int)fy, 0);
    const int hiy = min(max((int)ceilf(cy), 0), rh - 1);
    const float wy = cy - fy;
    const int y0 = ry + loy;
    const int y1 = ry + hiy;

    // All offsets fit in uint32 (image = 33.5M floats, out = 12.8M floats).
    const unsigned t = threadIdx.x;         // 256 threads * float4 = 1024 ch
    const unsigned base_b = (unsigned)b * (IMG_H * IMG_W * (CH / 4));  // float4 units
    const unsigned row0 = base_b + ((unsigned)y0 * IMG_W) * (CH / 4) + t;
    const unsigned row1 = base_b + ((unsigned)y1 * IMG_W) * (CH / 4) + t;

    const float4* __restrict__ img4 = (const float4*)img;

    const float4 a = __ldg(img4 + row0 + (unsigned)x0 * (CH / 4));
    const float4 bq = __ldg(img4 + row0 + (unsigned)x1 * (CH / 4));
    const float4 c = __ldg(img4 + row1 + (unsigned)x0 * (CH / 4));
    const float4 d = __ldg(img4 + row1 + (unsigned)x1 * (CH / 4));

    float4 res;
    {
        float top, bot;
        top = a.x + (bq.x - a.x) * wx;
        bot = c.x + (d.x - c.x) * wx;
        res.x = top + (bot - top) * wy;
        top = a.y + (bq.y - a.y) * wx;
        bot = c.y + (d.y - c.y) * wx;
        res.y = top + (bot - top) * wy;
        top = a.z + (bq.z - a.z) * wx;
        bot = c.z + (d.z - c.z) * wx;
        res.z = top + (bot - top) * wy;
        top = a.w + (bq.w - a.w) * wx;
        bot = c.w + (d.w - c.w) * wx;
        res.w = top + (bot - top) * wy;
    }

    __stcs((float4*)out + (unsigned)flat * (CH / 4) + t, res);
}

extern "C" void kernel_launch(void* const* d_in, const int* in_sizes, int n_in,
                              void* d_out, int out_size)
{
    const float* img  = (const float*)d_in[0];
    const int*   rois = (const int*)d_in[1];
    float*       out  = (float*)d_out;

    roi_align_kernel_v10<<<N_TILES, 256>>>(img, rois, out);
}